// round 8
// baseline (speedup 1.0000x reference)
#include <cuda_runtime.h>

#define BB 4
#define CC 64
#define HH 192
#define WWI 192
#define HWSZ (HH*WWI)
#define HD 96
#define WD 96

// ---- scratch (static device globals; no runtime allocation) ----
__device__ float g_down[BB*CC*HD*WD];          // 9.4 MB
__device__ float g_df[BB*HWSZ];
__device__ float g_nsq[BB*HWSZ];
__device__ unsigned g_dfmin[BB];
__device__ unsigned g_dfmax[BB];
__device__ float g_sum[BB*CC];
__device__ float g_ssq[BB*CC];

typedef unsigned long long ull;

__device__ __forceinline__ ull pack2(float lo, float hi) {
    ull r; asm("mov.b64 %0, {%1, %2};" : "=l"(r) : "f"(lo), "f"(hi)); return r;
}
__device__ __forceinline__ void unpack2(ull v, float& lo, float& hi) {
    asm("mov.b64 {%0, %1}, %2;" : "=f"(lo), "=f"(hi) : "l"(v));
}
__device__ __forceinline__ ull fma2(ull a, ull b, ull c) {
    ull d; asm("fma.rn.f32x2 %0, %1, %2, %3;" : "=l"(d) : "l"(a), "l"(b), "l"(c)); return d;
}

__global__ void k_init() {
    int t = blockIdx.x * 256 + threadIdx.x;
    if (t < BB) { g_dfmin[t] = 0x7f800000u; g_dfmax[t] = 0u; }
    if (t < BB*CC) { g_sum[t] = 0.f; g_ssq[t] = 0.f; }
}

// 0.5x bilinear == 2x2 average pooling; also accumulates GroupNorm sum/sumsq.
__global__ void k_down(const float* __restrict__ x) {
    int blk  = blockIdx.x;
    int bc   = blk >> 1;
    int half = blk & 1;
    const float* xp = x + (size_t)bc * HWSZ;
    float* dp = g_down + (size_t)bc * (HD*WD);

    float s = 0.f, q = 0.f;
    for (int idx = threadIdx.x; idx < 48*48; idx += 256) {
        int jp = idx % 48;
        int r  = idx / 48;
        int ii = half * 48 + r;
        const float4 v0 = *(const float4*)(xp + (2*ii)   * WWI + 4*jp);
        const float4 v1 = *(const float4*)(xp + (2*ii+1) * WWI + 4*jp);
        float o0 = 0.5f*(0.5f*v0.x + 0.5f*v1.x) + 0.5f*(0.5f*v0.y + 0.5f*v1.y);
        float o1 = 0.5f*(0.5f*v0.z + 0.5f*v1.z) + 0.5f*(0.5f*v0.w + 0.5f*v1.w);
        dp[ii*WD + 2*jp]   = o0;
        dp[ii*WD + 2*jp+1] = o1;
        s += ((v0.x+v0.y)+(v0.z+v0.w)) + ((v1.x+v1.y)+(v1.z+v1.w));
        q += ((v0.x*v0.x+v0.y*v0.y)+(v0.z*v0.z+v0.w*v0.w))
           + ((v1.x*v1.x+v1.y*v1.y)+(v1.z*v1.z+v1.w*v1.w));
    }
    __shared__ float ss[256], sq[256];
    ss[threadIdx.x] = s; sq[threadIdx.x] = q;
    __syncthreads();
    for (int st = 128; st > 0; st >>= 1) {
        if (threadIdx.x < st) {
            ss[threadIdx.x] += ss[threadIdx.x+st];
            sq[threadIdx.x] += sq[threadIdx.x+st];
        }
        __syncthreads();
    }
    if (threadIdx.x == 0) {
        atomicAdd(&g_sum[bc], ss[0]);
        atomicAdd(&g_ssq[bc], sq[0]);
    }
}

// df map (sum_c |x - up(down(x))|), per-pixel normsq over C, per-batch min/max
__global__ void k_df(const float* __restrict__ x) {
    int p = blockIdx.x * 256 + threadIdx.x;
    int b = blockIdx.y;
    int h = p / WWI, w = p % WWI;

    float sh = fminf(fmaxf((h + 0.5f) * 0.5f - 0.5f, 0.f), (float)(HD-1));
    float sw = fminf(fmaxf((w + 0.5f) * 0.5f - 0.5f, 0.f), (float)(WD-1));
    int hl = (int)sh; int hh2 = min(hl+1, HD-1); float wh = sh - (float)hl;
    int wl = (int)sw; int wh2 = min(wl+1, WD-1); float ww = sw - (float)wl;
    int i00 = hl*WD+wl, i10 = hh2*WD+wl, i01 = hl*WD+wh2, i11 = hh2*WD+wh2;

    const float* xb = x + (size_t)b * CC * HWSZ + p;
    const float* db = g_down + (size_t)b * CC * HD * WD;

    float df = 0.f, nsq = 0.f;
    #pragma unroll 8
    for (int c = 0; c < CC; c++) {
        float xv = xb[(size_t)c * HWSZ];
        const float* dc = db + c * HD * WD;
        float u0  = dc[i00]*(1.f-wh) + dc[i10]*wh;
        float u1  = dc[i01]*(1.f-wh) + dc[i11]*wh;
        float xdu = u0*(1.f-ww) + u1*ww;
        df  += fabsf(xv - xdu);
        nsq += xv * xv;
    }
    g_df[b*HWSZ+p]  = df;
    g_nsq[b*HWSZ+p] = nsq;

    __shared__ float smn[256], smx[256];
    int tid = threadIdx.x;
    smn[tid] = df; smx[tid] = df;
    __syncthreads();
    for (int s = 128; s > 0; s >>= 1) {
        if (tid < s) {
            smn[tid] = fminf(smn[tid], smn[tid+s]);
            smx[tid] = fmaxf(smx[tid], smx[tid+s]);
        }
        __syncthreads();
    }
    if (tid == 0) {
        atomicMin(&g_dfmin[b], __float_as_uint(smn[0]));
        atomicMax(&g_dfmax[b], __float_as_uint(smx[0]));
    }
}

// ---------------- persistent fused kernel ----------------
// Per 64-pixel tile: phase A (detail gating + cosine top-k + GN add) -> sE,
// then register-tiled FFN GEMM: out = E + W2 @ relu(W1 @ E + b1) + b2.
// smem: sE[64c][64px] 16KB | sW1t 32KB | sW2t 32KB | sH 32KB | b1 | b2 | Aff | Bff
#define SM_E    0
#define SM_W1T  4096
#define SM_W2T  (4096+8192)
#define SM_H    (4096+8192+8192)
#define SM_B1   (4096+8192+8192+8192)
#define SM_B2   (SM_B1+128)
#define SM_AF   (SM_B2+64)
#define SM_BF   (SM_AF+64)
#define SM_TOT  (SM_BF+64)
#define NTILES  ((BB*HWSZ)/64)     // 2304

__global__ void __launch_bounds__(256, 2) k_ffn(
    const float* __restrict__ x,
    const float* __restrict__ gw, const float* __restrict__ gb,
    const float* __restrict__ w1, const float* __restrict__ b1,
    const float* __restrict__ w2, const float* __restrict__ b2,
    float* __restrict__ out)
{
    extern __shared__ float sm[];
    int tid = threadIdx.x;

    // ---- one-time weight staging ----
    for (int i = tid; i < 8192; i += 256) {        // sW1t[c][o] = w1[o][c]
        int c = i >> 7, o = i & 127;
        sm[SM_W1T + i] = w1[o * 64 + c];
    }
    for (int i = tid; i < 8192; i += 256) {        // sW2t[o][c] = w2[c][o]
        int o = i >> 6, c = i & 63;
        sm[SM_W2T + i] = w2[c * 128 + o];
    }
    if (tid < 128) sm[SM_B1 + tid] = b1[tid];
    if (tid < 64)  sm[SM_B2 + tid] = b2[tid];

    // GEMM thread tiling
    int og = tid >> 4, pg = tid & 15;
    int ob = og * 8, pb = pg * 4, cb = og * 4;
    // phase-A tiling: 4 threads per pixel, 16 channels each
    int pxA = tid >> 2, subA = tid & 3, c0a = subA * 16;
    int lane = tid & 31;
    unsigned pmask = 0xFu << (lane & ~3u);

    for (int tile = blockIdx.x; tile < NTILES; tile += gridDim.x) {
        int b  = tile / (HWSZ/64);
        int p0 = (tile - b * (HWSZ/64)) * 64;

        __syncthreads();   // prior tile fully done with sE/sH/sAff

        if (tid < 64) {    // GroupNorm affine fold for this batch (cheap)
            int c = tid, g = c >> 1;
            int base = b * CC + 2 * g;
            float n2  = 2.f * (float)HWSZ;
            float mu  = (g_sum[base] + g_sum[base+1]) / n2;
            float var = (g_ssq[base] + g_ssq[base+1]) / n2 - mu*mu;
            float inv = rsqrtf(var + 1e-5f);
            float A = gw[c] * inv;
            sm[SM_AF + c] = A;
            sm[SM_BF + c] = gb[c] - mu * A;
        }
        __syncthreads();

        // ================= phase A: enhanced -> sE =================
        {
            int p = p0 + pxA;
            int h = p / WWI, w = p % WWI;
            const float* xbA = x + (size_t)b * CC * HWSZ + (size_t)c0a * HWSZ + p;
            float* sEp = sm + SM_E + c0a * 64 + pxA;

            float dmin = __uint_as_float(g_dfmin[b]);
            float dmax = __uint_as_float(g_dfmax[b]);
            float df   = g_df[b*HWSZ + p];
            float t0   = (df - dmin) / ((dmax - dmin) + 1e-8f);
            float dfp  = t0 * t0;

            if (!(dfp > 0.3f)) {   // not processed: enhanced = x + (A*x+B)
                #pragma unroll
                for (int c = 0; c < 16; c++) {
                    float xv = xbA[(size_t)c * HWSZ];
                    sEp[c * 64] = xv + (sm[SM_AF + c0a + c]*xv + sm[SM_BF + c0a + c]);
                }
            } else {
                int kk = min(1 + (int)rintf(dfp * 15.f), 9);

                bool val[9];
                int  doff[9];
                #pragma unroll
                for (int j = 0; j < 9; j++) {
                    int dy = j/3 - 1, dx = j - 3*(j/3) - 1;
                    val[j]  = ((unsigned)(h+dy) < HH) && ((unsigned)(w+dx) < WWI);
                    doff[j] = dy * WWI + dx;
                }

                float dot[9];
                #pragma unroll
                for (int j = 0; j < 9; j++) dot[j] = 0.f;

                #pragma unroll 4
                for (int c = 0; c < 16; c++) {
                    const float* rc = xbA + (size_t)c * HWSZ;
                    float xv = rc[0];
                    #pragma unroll
                    for (int j = 0; j < 9; j++)
                        if (val[j]) dot[j] = fmaf(xv, rc[doff[j]], dot[j]);
                }
                #pragma unroll
                for (int j = 0; j < 9; j++) {   // combine 4 channel groups
                    dot[j] += __shfl_xor_sync(pmask, dot[j], 1);
                    dot[j] += __shfl_xor_sync(pmask, dot[j], 2);
                }

                float ncen = fmaxf(sqrtf(g_nsq[b*HWSZ + p]), 1e-12f);
                float sim[9];
                #pragma unroll
                for (int j = 0; j < 9; j++) {
                    if (val[j]) {
                        float nn = fmaxf(sqrtf(g_nsq[b*HWSZ + p + doff[j]]), 1e-12f);
                        sim[j] = dot[j] / (ncen * nn);
                    } else {
                        sim[j] = 0.f;
                    }
                }

                // stable top-k via rank, in registers (identical across the 4 subs)
                float wt[9];
                float wsum = 0.f;
                #pragma unroll
                for (int j = 0; j < 9; j++) {
                    int rank = 0;
                    #pragma unroll
                    for (int l = 0; l < 9; l++) {
                        if (l != j) {
                            bool beats = (sim[l] > sim[j]) || (sim[l] == sim[j] && l < j);
                            rank += beats ? 1 : 0;
                        }
                    }
                    float wv = (rank < kk) ? expf(sim[j]) : 0.f;
                    wt[j] = wv;
                    wsum += wv;
                }
                float invw = 1.f / fmaxf(wsum, 1e-12f);
                #pragma unroll
                for (int j = 0; j < 9; j++) wt[j] *= invw;

                #pragma unroll 4
                for (int c = 0; c < 16; c++) {
                    const float* rc = xbA + (size_t)c * HWSZ;
                    float acc = 0.f;
                    #pragma unroll
                    for (int j = 0; j < 9; j++)
                        if (val[j]) acc = fmaf(wt[j], rc[doff[j]], acc);
                    float xv = rc[0];
                    sEp[c * 64] = acc + (sm[SM_AF + c0a + c]*xv + sm[SM_BF + c0a + c]);
                }
            }
        }
        __syncthreads();

        // ================= GEMM1: H = relu(W1 @ E + b1), 8o x 4px =================
        ull acc1[4][4];
        #pragma unroll
        for (int i = 0; i < 4; i++)
            #pragma unroll
            for (int j = 0; j < 4; j++) acc1[i][j] = 0ull;

        #pragma unroll 4
        for (int c = 0; c < 64; c++) {
            const ulonglong2* wp = (const ulonglong2*)(sm + SM_W1T + c*128 + ob);
            ulonglong2 wA = wp[0], wB = wp[1];
            float4 ev = *(const float4*)(sm + SM_E + c*64 + pb);
            ull e0 = pack2(ev.x, ev.x), e1 = pack2(ev.y, ev.y);
            ull e2 = pack2(ev.z, ev.z), e3 = pack2(ev.w, ev.w);
            acc1[0][0] = fma2(wA.x, e0, acc1[0][0]);
            acc1[0][1] = fma2(wA.x, e1, acc1[0][1]);
            acc1[0][2] = fma2(wA.x, e2, acc1[0][2]);
            acc1[0][3] = fma2(wA.x, e3, acc1[0][3]);
            acc1[1][0] = fma2(wA.y, e0, acc1[1][0]);
            acc1[1][1] = fma2(wA.y, e1, acc1[1][1]);
            acc1[1][2] = fma2(wA.y, e2, acc1[1][2]);
            acc1[1][3] = fma2(wA.y, e3, acc1[1][3]);
            acc1[2][0] = fma2(wB.x, e0, acc1[2][0]);
            acc1[2][1] = fma2(wB.x, e1, acc1[2][1]);
            acc1[2][2] = fma2(wB.x, e2, acc1[2][2]);
            acc1[2][3] = fma2(wB.x, e3, acc1[2][3]);
            acc1[3][0] = fma2(wB.y, e0, acc1[3][0]);
            acc1[3][1] = fma2(wB.y, e1, acc1[3][1]);
            acc1[3][2] = fma2(wB.y, e2, acc1[3][2]);
            acc1[3][3] = fma2(wB.y, e3, acc1[3][3]);
        }

        #pragma unroll
        for (int i = 0; i < 4; i++) {
            float lo0, hi0, lo1, hi1, lo2, hi2, lo3, hi3;
            unpack2(acc1[i][0], lo0, hi0);
            unpack2(acc1[i][1], lo1, hi1);
            unpack2(acc1[i][2], lo2, hi2);
            unpack2(acc1[i][3], lo3, hi3);
            int oo = ob + 2*i;
            float bl = sm[SM_B1 + oo], bh = sm[SM_B1 + oo + 1];
            float4 rl = { fmaxf(lo0+bl,0.f), fmaxf(lo1+bl,0.f), fmaxf(lo2+bl,0.f), fmaxf(lo3+bl,0.f) };
            float4 rh = { fmaxf(hi0+bh,0.f), fmaxf(hi1+bh,0.f), fmaxf(hi2+bh,0.f), fmaxf(hi3+bh,0.f) };
            *(float4*)(sm + SM_H + (oo)   * 64 + pb) = rl;
            *(float4*)(sm + SM_H + (oo+1) * 64 + pb) = rh;
        }
        __syncthreads();

        // ================= GEMM2: OUT = E + W2 @ H + b2, 4c x 4px =================
        ull acc2[2][4];
        #pragma unroll
        for (int i = 0; i < 2; i++) {
            int c = cb + 2*i;
            float b2l = sm[SM_B2 + c], b2h = sm[SM_B2 + c + 1];
            const float* el = sm + SM_E + c*64 + pb;
            const float* eh = sm + SM_E + (c+1)*64 + pb;
            #pragma unroll
            for (int j = 0; j < 4; j++)
                acc2[i][j] = pack2(el[j] + b2l, eh[j] + b2h);
        }

        #pragma unroll 4
        for (int o = 0; o < 128; o++) {
            ulonglong2 wv = *(const ulonglong2*)(sm + SM_W2T + o*64 + cb);
            float4 hv = *(const float4*)(sm + SM_H + o*64 + pb);
            ull h0 = pack2(hv.x, hv.x), h1 = pack2(hv.y, hv.y);
            ull h2 = pack2(hv.z, hv.z), h3 = pack2(hv.w, hv.w);
            acc2[0][0] = fma2(wv.x, h0, acc2[0][0]);
            acc2[0][1] = fma2(wv.x, h1, acc2[0][1]);
            acc2[0][2] = fma2(wv.x, h2, acc2[0][2]);
            acc2[0][3] = fma2(wv.x, h3, acc2[0][3]);
            acc2[1][0] = fma2(wv.y, h0, acc2[1][0]);
            acc2[1][1] = fma2(wv.y, h1, acc2[1][1]);
            acc2[1][2] = fma2(wv.y, h2, acc2[1][2]);
            acc2[1][3] = fma2(wv.y, h3, acc2[1][3]);
        }

        float* O = out + (size_t)b * CC * HWSZ + p0;
        #pragma unroll
        for (int i = 0; i < 2; i++) {
            float lo0, hi0, lo1, hi1, lo2, hi2, lo3, hi3;
            unpack2(acc2[i][0], lo0, hi0);
            unpack2(acc2[i][1], lo1, hi1);
            unpack2(acc2[i][2], lo2, hi2);
            unpack2(acc2[i][3], lo3, hi3);
            int c = cb + 2*i;
            float4 vl = { lo0, lo1, lo2, lo3 };
            float4 vh = { hi0, hi1, hi2, hi3 };
            *(float4*)(O + (size_t)c     * HWSZ + pb) = vl;
            *(float4*)(O + (size_t)(c+1) * HWSZ + pb) = vh;
        }
    }
}

extern "C" void kernel_launch(void* const* d_in, const int* in_sizes, int n_in,
                              void* d_out, int out_size) {
    const float* x  = (const float*)d_in[0];
    const float* gw = (const float*)d_in[1];
    const float* gb = (const float*)d_in[2];
    const float* w1 = (const float*)d_in[3];
    const float* b1 = (const float*)d_in[4];
    const float* w2 = (const float*)d_in[5];
    const float* b2 = (const float*)d_in[6];
    float* out = (float*)d_out;

    k_init<<<1, 256>>>();
    k_down<<<BB*CC*2, 256>>>(x);
    k_df<<<dim3(HWSZ/256, BB), 256>>>(x);

    size_t smem = (size_t)SM_TOT * sizeof(float);
    cudaFuncSetAttribute(k_ffn, cudaFuncAttributeMaxDynamicSharedMemorySize, (int)smem);
    k_ffn<<<296, 256, smem>>>(x, gw, gb, w1, b1, w2, b2, out);
}

// round 9
// speedup vs baseline: 1.1935x; 1.1935x over previous
#include <cuda_runtime.h>

#define BB 4
#define CC 64
#define HH 192
#define WWI 192
#define HWSZ (HH*WWI)
#define HD 96
#define WD 96

// ---- scratch (static device globals; no runtime allocation) ----
__device__ float g_down[BB*CC*HD*WD];          // 9.4 MB
__device__ float g_df[BB*HWSZ];
__device__ float g_nsq[BB*HWSZ];
__device__ unsigned g_dfmin[BB];
__device__ unsigned g_dfmax[BB];
__device__ float g_sum[BB*CC];
__device__ float g_ssq[BB*CC];

typedef unsigned long long ull;

__device__ __forceinline__ ull pack2(float lo, float hi) {
    ull r; asm("mov.b64 %0, {%1, %2};" : "=l"(r) : "f"(lo), "f"(hi)); return r;
}
__device__ __forceinline__ void unpack2(ull v, float& lo, float& hi) {
    asm("mov.b64 {%0, %1}, %2;" : "=f"(lo), "=f"(hi) : "l"(v));
}
__device__ __forceinline__ ull fma2(ull a, ull b, ull c) {
    ull d; asm("fma.rn.f32x2 %0, %1, %2, %3;" : "=l"(d) : "l"(a), "l"(b), "l"(c)); return d;
}

__global__ void k_init() {
    int t = blockIdx.x * 256 + threadIdx.x;
    if (t < BB) { g_dfmin[t] = 0x7f800000u; g_dfmax[t] = 0u; }
    if (t < BB*CC) { g_sum[t] = 0.f; g_ssq[t] = 0.f; }
}

// 0.5x bilinear == 2x2 average pooling; also accumulates GroupNorm sum/sumsq.
__global__ void k_down(const float* __restrict__ x) {
    int blk  = blockIdx.x;
    int bc   = blk >> 1;
    int half = blk & 1;
    const float* xp = x + (size_t)bc * HWSZ;
    float* dp = g_down + (size_t)bc * (HD*WD);

    float s = 0.f, q = 0.f;
    for (int idx = threadIdx.x; idx < 48*48; idx += 256) {
        int jp = idx % 48;
        int r  = idx / 48;
        int ii = half * 48 + r;
        const float4 v0 = *(const float4*)(xp + (2*ii)   * WWI + 4*jp);
        const float4 v1 = *(const float4*)(xp + (2*ii+1) * WWI + 4*jp);
        float o0 = 0.5f*(0.5f*v0.x + 0.5f*v1.x) + 0.5f*(0.5f*v0.y + 0.5f*v1.y);
        float o1 = 0.5f*(0.5f*v0.z + 0.5f*v1.z) + 0.5f*(0.5f*v0.w + 0.5f*v1.w);
        dp[ii*WD + 2*jp]   = o0;
        dp[ii*WD + 2*jp+1] = o1;
        s += ((v0.x+v0.y)+(v0.z+v0.w)) + ((v1.x+v1.y)+(v1.z+v1.w));
        q += ((v0.x*v0.x+v0.y*v0.y)+(v0.z*v0.z+v0.w*v0.w))
           + ((v1.x*v1.x+v1.y*v1.y)+(v1.z*v1.z+v1.w*v1.w));
    }
    __shared__ float ss[256], sq[256];
    ss[threadIdx.x] = s; sq[threadIdx.x] = q;
    __syncthreads();
    for (int st = 128; st > 0; st >>= 1) {
        if (threadIdx.x < st) {
            ss[threadIdx.x] += ss[threadIdx.x+st];
            sq[threadIdx.x] += sq[threadIdx.x+st];
        }
        __syncthreads();
    }
    if (threadIdx.x == 0) {
        atomicAdd(&g_sum[bc], ss[0]);
        atomicAdd(&g_ssq[bc], sq[0]);
    }
}

// df map (sum_c |x - up(down(x))|), per-pixel normsq over C, per-batch min/max
__global__ void k_df(const float* __restrict__ x) {
    int p = blockIdx.x * 256 + threadIdx.x;
    int b = blockIdx.y;
    int h = p / WWI, w = p % WWI;

    float sh = fminf(fmaxf((h + 0.5f) * 0.5f - 0.5f, 0.f), (float)(HD-1));
    float sw = fminf(fmaxf((w + 0.5f) * 0.5f - 0.5f, 0.f), (float)(WD-1));
    int hl = (int)sh; int hh2 = min(hl+1, HD-1); float wh = sh - (float)hl;
    int wl = (int)sw; int wh2 = min(wl+1, WD-1); float ww = sw - (float)wl;
    int i00 = hl*WD+wl, i10 = hh2*WD+wl, i01 = hl*WD+wh2, i11 = hh2*WD+wh2;

    const float* xb = x + (size_t)b * CC * HWSZ + p;
    const float* db = g_down + (size_t)b * CC * HD * WD;

    float df = 0.f, nsq = 0.f;
    #pragma unroll 8
    for (int c = 0; c < CC; c++) {
        float xv = xb[(size_t)c * HWSZ];
        const float* dc = db + c * HD * WD;
        float u0  = dc[i00]*(1.f-wh) + dc[i10]*wh;
        float u1  = dc[i01]*(1.f-wh) + dc[i11]*wh;
        float xdu = u0*(1.f-ww) + u1*ww;
        df  += fabsf(xv - xdu);
        nsq += xv * xv;
    }
    g_df[b*HWSZ+p]  = df;
    g_nsq[b*HWSZ+p] = nsq;

    __shared__ float smn[256], smx[256];
    int tid = threadIdx.x;
    smn[tid] = df; smx[tid] = df;
    __syncthreads();
    for (int s = 128; s > 0; s >>= 1) {
        if (tid < s) {
            smn[tid] = fminf(smn[tid], smn[tid+s]);
            smx[tid] = fmaxf(smx[tid], smx[tid+s]);
        }
        __syncthreads();
    }
    if (tid == 0) {
        atomicMin(&g_dfmin[b], __float_as_uint(smn[0]));
        atomicMax(&g_dfmax[b], __float_as_uint(smx[0]));
    }
}

// ---------------- persistent fused kernel ----------------
// Per 64-pixel tile: phase A (detail gating + cosine top-k + GN add) -> sE,
// then register-tiled FFN GEMM: out = E + W2 @ relu(W1 @ E + b1) + b2.
// smem: sE 16KB | sW1t 32KB | sW2t 32KB | sH 32KB | b1 | b2   (112.75 KB, 2 CTAs/SM)
// GN affine A/B live INSIDE sH (dead during phase A) -> no extra smem vs R7.
#define SM_E    0
#define SM_W1T  4096
#define SM_W2T  (4096+8192)
#define SM_H    (4096+8192+8192)
#define SM_AF   SM_H
#define SM_BF   (SM_H+64)
#define SM_B1   (4096+8192+8192+8192)
#define SM_B2   (SM_B1+128)
#define SM_TOT  (SM_B2+64)
#define NTILES  ((BB*HWSZ)/64)     // 2304

__global__ void __launch_bounds__(256, 2) k_ffn(
    const float* __restrict__ x,
    const float* __restrict__ gw, const float* __restrict__ gb,
    const float* __restrict__ w1, const float* __restrict__ b1,
    const float* __restrict__ w2, const float* __restrict__ b2,
    float* __restrict__ out)
{
    extern __shared__ float sm[];
    int tid = threadIdx.x;

    // ---- one-time weight staging ----
    for (int i = tid; i < 8192; i += 256) {        // sW1t[c][o] = w1[o][c]
        int c = i >> 7, o = i & 127;
        sm[SM_W1T + i] = w1[o * 64 + c];
    }
    for (int i = tid; i < 8192; i += 256) {        // sW2t[o][c] = w2[c][o]
        int o = i >> 6, c = i & 63;
        sm[SM_W2T + i] = w2[c * 128 + o];
    }
    if (tid < 128) sm[SM_B1 + tid] = b1[tid];
    if (tid < 64)  sm[SM_B2 + tid] = b2[tid];

    // GEMM thread tiling
    int og = tid >> 4, pg = tid & 15;
    int ob = og * 8, pb = pg * 4, cb = og * 4;
    // phase-A tiling: 4 threads per pixel, 16 channels each
    int pxA = tid >> 2, subA = tid & 3, c0a = subA * 16;
    int lane = tid & 31;
    unsigned pmask = 0xFu << (lane & ~3u);

    for (int tile = blockIdx.x; tile < NTILES; tile += gridDim.x) {
        int b  = tile / (HWSZ/64);
        int p0 = (tile - b * (HWSZ/64)) * 64;

        __syncthreads();   // prior tile fully done with sE/sH (incl. AF/BF region)

        if (tid < 64) {    // GroupNorm affine fold for this batch (cheap) -> sH region
            int c = tid, g = c >> 1;
            int base = b * CC + 2 * g;
            float n2  = 2.f * (float)HWSZ;
            float mu  = (g_sum[base] + g_sum[base+1]) / n2;
            float var = (g_ssq[base] + g_ssq[base+1]) / n2 - mu*mu;
            float inv = rsqrtf(var + 1e-5f);
            float A = gw[c] * inv;
            sm[SM_AF + c] = A;
            sm[SM_BF + c] = gb[c] - mu * A;
        }
        __syncthreads();

        // ================= phase A: enhanced -> sE =================
        {
            int p = p0 + pxA;
            int h = p / WWI, w = p % WWI;
            const float* xbA = x + (size_t)b * CC * HWSZ + (size_t)c0a * HWSZ + p;
            float* sEp = sm + SM_E + c0a * 64 + pxA;

            float dmin = __uint_as_float(g_dfmin[b]);
            float dmax = __uint_as_float(g_dfmax[b]);
            float df   = g_df[b*HWSZ + p];
            float t0   = (df - dmin) / ((dmax - dmin) + 1e-8f);
            float dfp  = t0 * t0;

            if (!(dfp > 0.3f)) {   // not processed: enhanced = x + (A*x+B)
                #pragma unroll
                for (int c = 0; c < 16; c++) {
                    float xv = xbA[(size_t)c * HWSZ];
                    sEp[c * 64] = xv + (sm[SM_AF + c0a + c]*xv + sm[SM_BF + c0a + c]);
                }
            } else {
                int kk = min(1 + (int)rintf(dfp * 15.f), 9);

                bool val[9];
                int  doff[9];
                #pragma unroll
                for (int j = 0; j < 9; j++) {
                    int dy = j/3 - 1, dx = j - 3*(j/3) - 1;
                    val[j]  = ((unsigned)(h+dy) < HH) && ((unsigned)(w+dx) < WWI);
                    doff[j] = dy * WWI + dx;
                }

                float dot[9];
                #pragma unroll
                for (int j = 0; j < 9; j++) dot[j] = 0.f;

                #pragma unroll 4
                for (int c = 0; c < 16; c++) {
                    const float* rc = xbA + (size_t)c * HWSZ;
                    float xv = rc[0];
                    #pragma unroll
                    for (int j = 0; j < 9; j++)
                        if (val[j]) dot[j] = fmaf(xv, rc[doff[j]], dot[j]);
                }
                #pragma unroll
                for (int j = 0; j < 9; j++) {   // combine 4 channel groups
                    dot[j] += __shfl_xor_sync(pmask, dot[j], 1);
                    dot[j] += __shfl_xor_sync(pmask, dot[j], 2);
                }

                float ncen = fmaxf(sqrtf(g_nsq[b*HWSZ + p]), 1e-12f);
                float sim[9];
                #pragma unroll
                for (int j = 0; j < 9; j++) {
                    if (val[j]) {
                        float nn = fmaxf(sqrtf(g_nsq[b*HWSZ + p + doff[j]]), 1e-12f);
                        sim[j] = dot[j] / (ncen * nn);
                    } else {
                        sim[j] = 0.f;
                    }
                }

                // stable top-k via rank, in registers (identical across the 4 subs)
                float wt[9];
                float wsum = 0.f;
                #pragma unroll
                for (int j = 0; j < 9; j++) {
                    int rank = 0;
                    #pragma unroll
                    for (int l = 0; l < 9; l++) {
                        if (l != j) {
                            bool beats = (sim[l] > sim[j]) || (sim[l] == sim[j] && l < j);
                            rank += beats ? 1 : 0;
                        }
                    }
                    float wv = (rank < kk) ? expf(sim[j]) : 0.f;
                    wt[j] = wv;
                    wsum += wv;
                }
                float invw = 1.f / fmaxf(wsum, 1e-12f);
                #pragma unroll
                for (int j = 0; j < 9; j++) wt[j] *= invw;

                #pragma unroll 4
                for (int c = 0; c < 16; c++) {
                    const float* rc = xbA + (size_t)c * HWSZ;
                    float acc = 0.f;
                    #pragma unroll
                    for (int j = 0; j < 9; j++)
                        if (val[j]) acc = fmaf(wt[j], rc[doff[j]], acc);
                    float xv = rc[0];
                    sEp[c * 64] = acc + (sm[SM_AF + c0a + c]*xv + sm[SM_BF + c0a + c]);
                }
            }
        }
        __syncthreads();

        // ================= GEMM1: H = relu(W1 @ E + b1), 8o x 4px =================
        ull acc1[4][4];
        #pragma unroll
        for (int i = 0; i < 4; i++)
            #pragma unroll
            for (int j = 0; j < 4; j++) acc1[i][j] = 0ull;

        #pragma unroll 4
        for (int c = 0; c < 64; c++) {
            const ulonglong2* wp = (const ulonglong2*)(sm + SM_W1T + c*128 + ob);
            ulonglong2 wA = wp[0], wB = wp[1];
            float4 ev = *(const float4*)(sm + SM_E + c*64 + pb);
            ull e0 = pack2(ev.x, ev.x), e1 = pack2(ev.y, ev.y);
            ull e2 = pack2(ev.z, ev.z), e3 = pack2(ev.w, ev.w);
            acc1[0][0] = fma2(wA.x, e0, acc1[0][0]);
            acc1[0][1] = fma2(wA.x, e1, acc1[0][1]);
            acc1[0][2] = fma2(wA.x, e2, acc1[0][2]);
            acc1[0][3] = fma2(wA.x, e3, acc1[0][3]);
            acc1[1][0] = fma2(wA.y, e0, acc1[1][0]);
            acc1[1][1] = fma2(wA.y, e1, acc1[1][1]);
            acc1[1][2] = fma2(wA.y, e2, acc1[1][2]);
            acc1[1][3] = fma2(wA.y, e3, acc1[1][3]);
            acc1[2][0] = fma2(wB.x, e0, acc1[2][0]);
            acc1[2][1] = fma2(wB.x, e1, acc1[2][1]);
            acc1[2][2] = fma2(wB.x, e2, acc1[2][2]);
            acc1[2][3] = fma2(wB.x, e3, acc1[2][3]);
            acc1[3][0] = fma2(wB.y, e0, acc1[3][0]);
            acc1[3][1] = fma2(wB.y, e1, acc1[3][1]);
            acc1[3][2] = fma2(wB.y, e2, acc1[3][2]);
            acc1[3][3] = fma2(wB.y, e3, acc1[3][3]);
        }

        #pragma unroll
        for (int i = 0; i < 4; i++) {
            float lo0, hi0, lo1, hi1, lo2, hi2, lo3, hi3;
            unpack2(acc1[i][0], lo0, hi0);
            unpack2(acc1[i][1], lo1, hi1);
            unpack2(acc1[i][2], lo2, hi2);
            unpack2(acc1[i][3], lo3, hi3);
            int oo = ob + 2*i;
            float bl = sm[SM_B1 + oo], bh = sm[SM_B1 + oo + 1];
            float4 rl = { fmaxf(lo0+bl,0.f), fmaxf(lo1+bl,0.f), fmaxf(lo2+bl,0.f), fmaxf(lo3+bl,0.f) };
            float4 rh = { fmaxf(hi0+bh,0.f), fmaxf(hi1+bh,0.f), fmaxf(hi2+bh,0.f), fmaxf(hi3+bh,0.f) };
            *(float4*)(sm + SM_H + (oo)   * 64 + pb) = rl;
            *(float4*)(sm + SM_H + (oo+1) * 64 + pb) = rh;
        }
        __syncthreads();

        // ================= GEMM2: OUT = E + W2 @ H + b2, 4c x 4px =================
        ull acc2[2][4];
        #pragma unroll
        for (int i = 0; i < 2; i++) {
            int c = cb + 2*i;
            float b2l = sm[SM_B2 + c], b2h = sm[SM_B2 + c + 1];
            const float* el = sm + SM_E + c*64 + pb;
            const float* eh = sm + SM_E + (c+1)*64 + pb;
            #pragma unroll
            for (int j = 0; j < 4; j++)
                acc2[i][j] = pack2(el[j] + b2l, eh[j] + b2h);
        }

        #pragma unroll 4
        for (int o = 0; o < 128; o++) {
            ulonglong2 wv = *(const ulonglong2*)(sm + SM_W2T + o*64 + cb);
            float4 hv = *(const float4*)(sm + SM_H + o*64 + pb);
            ull h0 = pack2(hv.x, hv.x), h1 = pack2(hv.y, hv.y);
            ull h2 = pack2(hv.z, hv.z), h3 = pack2(hv.w, hv.w);
            acc2[0][0] = fma2(wv.x, h0, acc2[0][0]);
            acc2[0][1] = fma2(wv.x, h1, acc2[0][1]);
            acc2[0][2] = fma2(wv.x, h2, acc2[0][2]);
            acc2[0][3] = fma2(wv.x, h3, acc2[0][3]);
            acc2[1][0] = fma2(wv.y, h0, acc2[1][0]);
            acc2[1][1] = fma2(wv.y, h1, acc2[1][1]);
            acc2[1][2] = fma2(wv.y, h2, acc2[1][2]);
            acc2[1][3] = fma2(wv.y, h3, acc2[1][3]);
        }

        float* O = out + (size_t)b * CC * HWSZ + p0;
        #pragma unroll
        for (int i = 0; i < 2; i++) {
            float lo0, hi0, lo1, hi1, lo2, hi2, lo3, hi3;
            unpack2(acc2[i][0], lo0, hi0);
            unpack2(acc2[i][1], lo1, hi1);
            unpack2(acc2[i][2], lo2, hi2);
            unpack2(acc2[i][3], lo3, hi3);
            int c = cb + 2*i;
            float4 vl = { lo0, lo1, lo2, lo3 };
            float4 vh = { hi0, hi1, hi2, hi3 };
            *(float4*)(O + (size_t)c     * HWSZ + pb) = vl;
            *(float4*)(O + (size_t)(c+1) * HWSZ + pb) = vh;
        }
    }
}

extern "C" void kernel_launch(void* const* d_in, const int* in_sizes, int n_in,
                              void* d_out, int out_size) {
    const float* x  = (const float*)d_in[0];
    const float* gw = (const float*)d_in[1];
    const float* gb = (const float*)d_in[2];
    const float* w1 = (const float*)d_in[3];
    const float* b1 = (const float*)d_in[4];
    const float* w2 = (const float*)d_in[5];
    const float* b2 = (const float*)d_in[6];
    float* out = (float*)d_out;

    k_init<<<1, 256>>>();
    k_down<<<BB*CC*2, 256>>>(x);
    k_df<<<dim3(HWSZ/256, BB), 256>>>(x);

    size_t smem = (size_t)SM_TOT * sizeof(float);
    cudaFuncSetAttribute(k_ffn, cudaFuncAttributeMaxDynamicSharedMemorySize, (int)smem);
    k_ffn<<<296, 256, smem>>>(x, gw, gb, w1, b1, w2, b2, out);
}

// round 10
// speedup vs baseline: 1.4458x; 1.2114x over previous
#include <cuda_runtime.h>

#define BB 4
#define CC 64
#define HH 192
#define WWI 192
#define HWSZ (HH*WWI)
#define HD 96
#define WD 96

// ---- scratch (static device globals; no runtime allocation) ----
__device__ float g_down[BB*CC*HD*WD];          // 9.4 MB
__device__ float g_df[BB*HWSZ];
__device__ float g_nsq[BB*HWSZ];
__device__ unsigned g_dfmin[BB];
__device__ unsigned g_dfmax[BB];
__device__ float g_sum[BB*CC];
__device__ float g_ssq[BB*CC];
__device__ float g_enh[(size_t)BB*CC*HWSZ];    // 37.7 MB

typedef unsigned long long ull;

__device__ __forceinline__ ull pack2(float lo, float hi) {
    ull r; asm("mov.b64 %0, {%1, %2};" : "=l"(r) : "f"(lo), "f"(hi)); return r;
}
__device__ __forceinline__ void unpack2(ull v, float& lo, float& hi) {
    asm("mov.b64 {%0, %1}, %2;" : "=f"(lo), "=f"(hi) : "l"(v));
}
__device__ __forceinline__ ull fma2(ull a, ull b, ull c) {
    ull d; asm("fma.rn.f32x2 %0, %1, %2, %3;" : "=l"(d) : "l"(a), "l"(b), "l"(c)); return d;
}

__global__ void k_init() {
    int t = blockIdx.x * 256 + threadIdx.x;
    if (t < BB) { g_dfmin[t] = 0x7f800000u; g_dfmax[t] = 0u; }
    if (t < BB*CC) { g_sum[t] = 0.f; g_ssq[t] = 0.f; }
}

// 0.5x bilinear == 2x2 average pooling; also accumulates GroupNorm sum/sumsq.
// grid = BB*CC*4 blocks of 128 threads; each block does 12 down-rows.
__global__ void k_down(const float* __restrict__ x) {
    int blk  = blockIdx.x;
    int bc   = blk >> 2;
    int quad = blk & 3;
    const float* xp = x + (size_t)bc * HWSZ;
    float* dp = g_down + (size_t)bc * (HD*WD);

    float s = 0.f, q = 0.f;
    for (int idx = threadIdx.x; idx < 12*48; idx += 128) {
        int jp = idx % 48;
        int r  = idx / 48;
        int ii = quad * 24 + r * 2;     // interleave rows a bit for coalescing spread
        // handle two rows per item? keep simple: rows quad*24 + r*2 and +1 in two halves
        // (12 items of r -> 24 rows total per quad via second pass below)
        const float4 v0 = *(const float4*)(xp + (2*ii)   * WWI + 4*jp);
        const float4 v1 = *(const float4*)(xp + (2*ii+1) * WWI + 4*jp);
        float o0 = 0.5f*(0.5f*v0.x + 0.5f*v1.x) + 0.5f*(0.5f*v0.y + 0.5f*v1.y);
        float o1 = 0.5f*(0.5f*v0.z + 0.5f*v1.z) + 0.5f*(0.5f*v0.w + 0.5f*v1.w);
        dp[ii*WD + 2*jp]   = o0;
        dp[ii*WD + 2*jp+1] = o1;
        s += ((v0.x+v0.y)+(v0.z+v0.w)) + ((v1.x+v1.y)+(v1.z+v1.w));
        q += ((v0.x*v0.x+v0.y*v0.y)+(v0.z*v0.z+v0.w*v0.w))
           + ((v1.x*v1.x+v1.y*v1.y)+(v1.z*v1.z+v1.w*v1.w));
        // second (odd) row of the pair
        int ii2 = ii + 1;
        const float4 u0 = *(const float4*)(xp + (2*ii2)   * WWI + 4*jp);
        const float4 u1 = *(const float4*)(xp + (2*ii2+1) * WWI + 4*jp);
        float p0 = 0.5f*(0.5f*u0.x + 0.5f*u1.x) + 0.5f*(0.5f*u0.y + 0.5f*u1.y);
        float p1 = 0.5f*(0.5f*u0.z + 0.5f*u1.z) + 0.5f*(0.5f*u0.w + 0.5f*u1.w);
        dp[ii2*WD + 2*jp]   = p0;
        dp[ii2*WD + 2*jp+1] = p1;
        s += ((u0.x+u0.y)+(u0.z+u0.w)) + ((u1.x+u1.y)+(u1.z+u1.w));
        q += ((u0.x*u0.x+u0.y*u0.y)+(u0.z*u0.z+u0.w*u0.w))
           + ((u1.x*u1.x+u1.y*u1.y)+(u1.z*u1.z+u1.w*u1.w));
    }
    __shared__ float ss[128], sq[128];
    ss[threadIdx.x] = s; sq[threadIdx.x] = q;
    __syncthreads();
    for (int st = 64; st > 0; st >>= 1) {
        if (threadIdx.x < st) {
            ss[threadIdx.x] += ss[threadIdx.x+st];
            sq[threadIdx.x] += sq[threadIdx.x+st];
        }
        __syncthreads();
    }
    if (threadIdx.x == 0) {
        atomicAdd(&g_sum[bc], ss[0]);
        atomicAdd(&g_ssq[bc], sq[0]);
    }
}

// df map (sum_c |x - up(down(x))|), per-pixel normsq over C, per-batch min/max
__global__ void k_df(const float* __restrict__ x) {
    int p = blockIdx.x * 128 + threadIdx.x;
    int b = blockIdx.y;
    int h = p / WWI, w = p % WWI;

    float sh = fminf(fmaxf((h + 0.5f) * 0.5f - 0.5f, 0.f), (float)(HD-1));
    float sw = fminf(fmaxf((w + 0.5f) * 0.5f - 0.5f, 0.f), (float)(WD-1));
    int hl = (int)sh; int hh2 = min(hl+1, HD-1); float wh = sh - (float)hl;
    int wl = (int)sw; int wh2 = min(wl+1, WD-1); float ww = sw - (float)wl;
    int i00 = hl*WD+wl, i10 = hh2*WD+wl, i01 = hl*WD+wh2, i11 = hh2*WD+wh2;

    const float* xb = x + (size_t)b * CC * HWSZ + p;
    const float* db = g_down + (size_t)b * CC * HD * WD;

    float df = 0.f, nsq = 0.f;
    #pragma unroll 8
    for (int c = 0; c < CC; c++) {
        float xv = xb[(size_t)c * HWSZ];
        const float* dc = db + c * HD * WD;
        float u0  = dc[i00]*(1.f-wh) + dc[i10]*wh;
        float u1  = dc[i01]*(1.f-wh) + dc[i11]*wh;
        float xdu = u0*(1.f-ww) + u1*ww;
        df  += fabsf(xv - xdu);
        nsq += xv * xv;
    }
    g_df[b*HWSZ+p]  = df;
    g_nsq[b*HWSZ+p] = nsq;

    __shared__ float smn[128], smx[128];
    int tid = threadIdx.x;
    smn[tid] = df; smx[tid] = df;
    __syncthreads();
    for (int s = 64; s > 0; s >>= 1) {
        if (tid < s) {
            smn[tid] = fminf(smn[tid], smn[tid+s]);
            smx[tid] = fmaxf(smx[tid], smx[tid+s]);
        }
        __syncthreads();
    }
    if (tid == 0) {
        atomicMin(&g_dfmin[b], __float_as_uint(smn[0]));
        atomicMax(&g_dfmax[b], __float_as_uint(smx[0]));
    }
}

// phase A: detail gating + cosine top-k aggregation + GroupNorm add -> g_enh
__global__ void __launch_bounds__(128) k_main(
    const float* __restrict__ x,
    const float* __restrict__ gw, const float* __restrict__ gb) {
    int p = blockIdx.x * 128 + threadIdx.x;
    int b = blockIdx.y;

    __shared__ float sA[CC], sB[CC];
    if (threadIdx.x < CC) {        // fold GN into per-(b,c) affine, per block
        int c = threadIdx.x, g = c >> 1;
        int base = b * CC + 2 * g;
        float n2  = 2.f * (float)HWSZ;
        float mu  = (g_sum[base] + g_sum[base+1]) / n2;
        float var = (g_ssq[base] + g_ssq[base+1]) / n2 - mu*mu;
        float inv = rsqrtf(var + 1e-5f);
        float A = gw[c] * inv;
        sA[c] = A;
        sB[c] = gb[c] - mu * A;
    }
    __syncthreads();

    int h = p / WWI, w = p % WWI;
    const float* xb = x + (size_t)b * CC * HWSZ + p;
    float* eb = g_enh + (size_t)b * CC * HWSZ + p;

    float dmin = __uint_as_float(g_dfmin[b]);
    float dmax = __uint_as_float(g_dfmax[b]);
    float df   = g_df[b*HWSZ + p];
    float t0   = (df - dmin) / ((dmax - dmin) + 1e-8f);
    float dfp  = t0 * t0;

    if (!(dfp > 0.3f)) {   // not processed: enhanced = x + (A*x+B)
        #pragma unroll 8
        for (int c = 0; c < CC; c++) {
            float xv = xb[(size_t)c * HWSZ];
            eb[(size_t)c * HWSZ] = xv + (sA[c]*xv + sB[c]);
        }
        return;
    }

    int kk = min(1 + (int)rintf(dfp * 15.f), 9);

    bool val[9];
    int  doff[9];
    #pragma unroll
    for (int j = 0; j < 9; j++) {
        int dy = j/3 - 1, dx = j - 3*(j/3) - 1;
        val[j]  = ((unsigned)(h+dy) < HH) && ((unsigned)(w+dx) < WWI);
        doff[j] = dy * WWI + dx;
    }

    float dot[9];
    #pragma unroll
    for (int j = 0; j < 9; j++) dot[j] = 0.f;

    #pragma unroll 4
    for (int c = 0; c < CC; c++) {
        const float* rc = xb + (size_t)c * HWSZ;
        float xv = rc[0];
        #pragma unroll
        for (int j = 0; j < 9; j++)
            if (val[j]) dot[j] = fmaf(xv, rc[doff[j]], dot[j]);
    }

    float ncen = fmaxf(sqrtf(g_nsq[b*HWSZ + p]), 1e-12f);
    float sim[9];
    #pragma unroll
    for (int j = 0; j < 9; j++) {
        if (val[j]) {
            float nn = fmaxf(sqrtf(g_nsq[b*HWSZ + p + doff[j]]), 1e-12f);
            sim[j] = dot[j] / (ncen * nn);
        } else {
            sim[j] = 0.f;
        }
    }

    // stable top-k via rank (== stable argsort of -sim), in registers
    float wt[9];
    float wsum = 0.f;
    #pragma unroll
    for (int j = 0; j < 9; j++) {
        int rank = 0;
        #pragma unroll
        for (int l = 0; l < 9; l++) {
            if (l != j) {
                bool beats = (sim[l] > sim[j]) || (sim[l] == sim[j] && l < j);
                rank += beats ? 1 : 0;
            }
        }
        float wv = (rank < kk) ? expf(sim[j]) : 0.f;
        wt[j] = wv;
        wsum += wv;
    }
    float invw = 1.f / fmaxf(wsum, 1e-12f);
    #pragma unroll
    for (int j = 0; j < 9; j++) wt[j] *= invw;

    #pragma unroll 4
    for (int c = 0; c < CC; c++) {
        const float* rc = xb + (size_t)c * HWSZ;
        float acc = 0.f;
        #pragma unroll
        for (int j = 0; j < 9; j++)
            if (val[j]) acc = fmaf(wt[j], rc[doff[j]], acc);
        float xv = rc[0];
        eb[(size_t)c * HWSZ] = acc + (sA[c]*xv + sB[c]);
    }
}

// ---------------- persistent register-tiled FFN GEMM (R7-proven) ----------------
// out = E + W2 @ relu(W1 @ E + b1) + b2. Weights staged ONCE per resident CTA.
#define SM_E    0
#define SM_W1T  4096
#define SM_W2T  (4096+8192)
#define SM_H    (4096+8192+8192)
#define SM_B1   (4096+8192+8192+8192)
#define SM_B2   (SM_B1+128)
#define SM_TOT  (SM_B2+64)
#define NTILES  ((BB*HWSZ)/64)     // 2304

__global__ void __launch_bounds__(256, 2) k_ffn(
    const float* __restrict__ w1, const float* __restrict__ b1,
    const float* __restrict__ w2, const float* __restrict__ b2,
    float* __restrict__ out)
{
    extern __shared__ float sm[];
    int tid = threadIdx.x;

    for (int i = tid; i < 8192; i += 256) {        // sW1t[c][o] = w1[o][c]
        int c = i >> 7, o = i & 127;
        sm[SM_W1T + i] = w1[o * 64 + c];
    }
    for (int i = tid; i < 8192; i += 256) {        // sW2t[o][c] = w2[c][o]
        int o = i >> 6, c = i & 63;
        sm[SM_W2T + i] = w2[c * 128 + o];
    }
    if (tid < 128) sm[SM_B1 + tid] = b1[tid];
    if (tid < 64)  sm[SM_B2 + tid] = b2[tid];

    int og = tid >> 4, pg = tid & 15;
    int ob = og * 8, pb = pg * 4, cb = og * 4;

    for (int tile = blockIdx.x; tile < NTILES; tile += gridDim.x) {
        int b  = tile / (HWSZ/64);
        int p0 = (tile - b * (HWSZ/64)) * 64;
        const float* E = g_enh + (size_t)b * CC * HWSZ + p0;

        __syncthreads();
        {
            #pragma unroll
            for (int r = 0; r < 4; r++) {
                int c   = (tid + r*256) >> 4;
                int px4 = (tid + r*256) & 15;
                float4 v = *(const float4*)(E + (size_t)c * HWSZ + px4*4);
                *(float4*)(sm + SM_E + c*64 + px4*4) = v;
            }
        }
        __syncthreads();

        // ---- GEMM1: H = relu(W1 @ E + b1), 8o x 4px ----
        ull acc1[4][4];
        #pragma unroll
        for (int i = 0; i < 4; i++)
            #pragma unroll
            for (int j = 0; j < 4; j++) acc1[i][j] = 0ull;

        #pragma unroll 4
        for (int c = 0; c < 64; c++) {
            const ulonglong2* wp = (const ulonglong2*)(sm + SM_W1T + c*128 + ob);
            ulonglong2 wA = wp[0], wB = wp[1];
            float4 ev = *(const float4*)(sm + SM_E + c*64 + pb);
            ull e0 = pack2(ev.x, ev.x), e1 = pack2(ev.y, ev.y);
            ull e2 = pack2(ev.z, ev.z), e3 = pack2(ev.w, ev.w);
            acc1[0][0] = fma2(wA.x, e0, acc1[0][0]);
            acc1[0][1] = fma2(wA.x, e1, acc1[0][1]);
            acc1[0][2] = fma2(wA.x, e2, acc1[0][2]);
            acc1[0][3] = fma2(wA.x, e3, acc1[0][3]);
            acc1[1][0] = fma2(wA.y, e0, acc1[1][0]);
            acc1[1][1] = fma2(wA.y, e1, acc1[1][1]);
            acc1[1][2] = fma2(wA.y, e2, acc1[1][2]);
            acc1[1][3] = fma2(wA.y, e3, acc1[1][3]);
            acc1[2][0] = fma2(wB.x, e0, acc1[2][0]);
            acc1[2][1] = fma2(wB.x, e1, acc1[2][1]);
            acc1[2][2] = fma2(wB.x, e2, acc1[2][2]);
            acc1[2][3] = fma2(wB.x, e3, acc1[2][3]);
            acc1[3][0] = fma2(wB.y, e0, acc1[3][0]);
            acc1[3][1] = fma2(wB.y, e1, acc1[3][1]);
            acc1[3][2] = fma2(wB.y, e2, acc1[3][2]);
            acc1[3][3] = fma2(wB.y, e3, acc1[3][3]);
        }

        #pragma unroll
        for (int i = 0; i < 4; i++) {
            float lo0, hi0, lo1, hi1, lo2, hi2, lo3, hi3;
            unpack2(acc1[i][0], lo0, hi0);
            unpack2(acc1[i][1], lo1, hi1);
            unpack2(acc1[i][2], lo2, hi2);
            unpack2(acc1[i][3], lo3, hi3);
            int oo = ob + 2*i;
            float bl = sm[SM_B1 + oo], bh = sm[SM_B1 + oo + 1];
            float4 rl = { fmaxf(lo0+bl,0.f), fmaxf(lo1+bl,0.f), fmaxf(lo2+bl,0.f), fmaxf(lo3+bl,0.f) };
            float4 rh = { fmaxf(hi0+bh,0.f), fmaxf(hi1+bh,0.f), fmaxf(hi2+bh,0.f), fmaxf(hi3+bh,0.f) };
            *(float4*)(sm + SM_H + (oo)   * 64 + pb) = rl;
            *(float4*)(sm + SM_H + (oo+1) * 64 + pb) = rh;
        }
        __syncthreads();

        // ---- GEMM2: OUT = E + W2 @ H + b2, 4c x 4px ----
        ull acc2[2][4];
        #pragma unroll
        for (int i = 0; i < 2; i++) {
            int c = cb + 2*i;
            float b2l = sm[SM_B2 + c], b2h = sm[SM_B2 + c + 1];
            const float* el = sm + SM_E + c*64 + pb;
            const float* eh = sm + SM_E + (c+1)*64 + pb;
            #pragma unroll
            for (int j = 0; j < 4; j++)
                acc2[i][j] = pack2(el[j] + b2l, eh[j] + b2h);
        }

        #pragma unroll 4
        for (int o = 0; o < 128; o++) {
            ulonglong2 wv = *(const ulonglong2*)(sm + SM_W2T + o*64 + cb);
            float4 hv = *(const float4*)(sm + SM_H + o*64 + pb);
            ull h0 = pack2(hv.x, hv.x), h1 = pack2(hv.y, hv.y);
            ull h2 = pack2(hv.z, hv.z), h3 = pack2(hv.w, hv.w);
            acc2[0][0] = fma2(wv.x, h0, acc2[0][0]);
            acc2[0][1] = fma2(wv.x, h1, acc2[0][1]);
            acc2[0][2] = fma2(wv.x, h2, acc2[0][2]);
            acc2[0][3] = fma2(wv.x, h3, acc2[0][3]);
            acc2[1][0] = fma2(wv.y, h0, acc2[1][0]);
            acc2[1][1] = fma2(wv.y, h1, acc2[1][1]);
            acc2[1][2] = fma2(wv.y, h2, acc2[1][2]);
            acc2[1][3] = fma2(wv.y, h3, acc2[1][3]);
        }

        float* O = out + (size_t)b * CC * HWSZ + p0;
        #pragma unroll
        for (int i = 0; i < 2; i++) {
            float lo0, hi0, lo1, hi1, lo2, hi2, lo3, hi3;
            unpack2(acc2[i][0], lo0, hi0);
            unpack2(acc2[i][1], lo1, hi1);
            unpack2(acc2[i][2], lo2, hi2);
            unpack2(acc2[i][3], lo3, hi3);
            int c = cb + 2*i;
            float4 vl = { lo0, lo1, lo2, lo3 };
            float4 vh = { hi0, hi1, hi2, hi3 };
            *(float4*)(O + (size_t)c     * HWSZ + pb) = vl;
            *(float4*)(O + (size_t)(c+1) * HWSZ + pb) = vh;
        }
    }
}

extern "C" void kernel_launch(void* const* d_in, const int* in_sizes, int n_in,
                              void* d_out, int out_size) {
    const float* x  = (const float*)d_in[0];
    const float* gw = (const float*)d_in[1];
    const float* gb = (const float*)d_in[2];
    const float* w1 = (const float*)d_in[3];
    const float* b1 = (const float*)d_in[4];
    const float* w2 = (const float*)d_in[5];
    const float* b2 = (const float*)d_in[6];
    float* out = (float*)d_out;

    k_init<<<1, 256>>>();
    k_down<<<BB*CC*4, 128>>>(x);
    k_df<<<dim3(HWSZ/128, BB), 128>>>(x);
    k_main<<<dim3(HWSZ/128, BB), 128>>>(x, gw, gb);

    size_t smem = (size_t)SM_TOT * sizeof(float);
    cudaFuncSetAttribute(k_ffn, cudaFuncAttributeMaxDynamicSharedMemorySize, (int)smem);
    k_ffn<<<296, 256, smem>>>(w1, b1, w2, b2, out);
}